// round 1
// baseline (speedup 1.0000x reference)
#include <cuda_runtime.h>
#include <stdint.h>

// Problem constants
#define HWC   (512*512)      // pixels per plane
#define NCH   64             // channels
#define NSEG  256            // segments
#define NB    4              // batch
#define CG    32             // channels per block (channel group)
#define NCG   (NCH/CG)       // channel groups = 2
#define CHUNK 4096           // pixels per block chunk (full plane = 64 chunks)
#define TPB   256

// Monotone float -> uint encoding: enc(a) < enc(b)  <=>  a < b (for non-NaN).
// enc(x) > 0 for every float >= -inf, so 0 is a safe "empty" sentinel.
__device__ __forceinline__ unsigned enc_f32(float f) {
    unsigned b = __float_as_uint(f);
    return b ^ ((unsigned)((int)b >> 31) | 0x80000000u);
}

__global__ void init_kernel(unsigned* __restrict__ out, int n) {
    int i = blockIdx.x * blockDim.x + threadIdx.x;
    if (i < n) out[i] = 0u;
}

__global__ __launch_bounds__(TPB) void seg_kernel(
    const float* __restrict__ feats,   // [B, C, 512, 512]
    const int*   __restrict__ labels,  // [B, 1, 512, 512]
    unsigned*    __restrict__ out)     // [B, C, NSEG] encoded
{
    // Per-block privatized table: CG channels x (NSEG + 1 dummy slot for border px).
    // Stride 257 (odd) -> good bank spread.
    __shared__ unsigned smax[CG][NSEG + 1];
    __shared__ unsigned short slab[CHUNK];

    const int tid   = threadIdx.x;
    const int chunk = blockIdx.x;          // 0..63
    const int cg    = blockIdx.y;          // 0..NCG-1
    const int b     = blockIdx.z;          // 0..3
    const int base  = chunk * CHUNK;       // plane-linear pixel base

    // Init table
    for (int i = tid; i < CG * (NSEG + 1); i += TPB)
        (&smax[0][0])[i] = 0u;

    // Load labels for this chunk; border pixels -> dummy segment NSEG.
    {
        const int* lb = labels + (size_t)b * HWC + base;
        for (int i = tid; i < CHUNK; i += TPB) {
            int p = base + i;
            int y = p >> 9;
            int x = p & 511;
            bool border = (y == 0) | (y == 511) | (x == 0) | (x == 511);
            slab[i] = border ? (unsigned short)NSEG : (unsigned short)lb[i];
        }
    }
    __syncthreads();

    // Stream features: outer loop channels, inner coalesced float4 over chunk.
    const float4* fbase =
        (const float4*)(feats + ((size_t)b * NCH + (size_t)cg * CG) * HWC + base);
    const int plane4 = HWC / 4;

    for (int c = 0; c < CG; ++c) {
        const float4* fc = fbase + (size_t)c * plane4;
        #pragma unroll
        for (int it = 0; it < (CHUNK / 4) / TPB; ++it) {
            int i = tid + it * TPB;
            float4 v = fc[i];
            int j = i * 4;
            unsigned short l0 = slab[j + 0];
            unsigned short l1 = slab[j + 1];
            unsigned short l2 = slab[j + 2];
            unsigned short l3 = slab[j + 3];
            atomicMax(&smax[c][l0], enc_f32(v.x));
            atomicMax(&smax[c][l1], enc_f32(v.y));
            atomicMax(&smax[c][l2], enc_f32(v.z));
            atomicMax(&smax[c][l3], enc_f32(v.w));
        }
    }
    __syncthreads();

    // Merge block-private table into global (encoded) output.
    unsigned* gout = out + ((size_t)b * NCH + (size_t)cg * CG) * NSEG;
    for (int i = tid; i < CG * NSEG; i += TPB) {
        int c = i >> 8;
        int s = i & 255;
        unsigned u = smax[c][s];
        if (u) atomicMax(&gout[c * NSEG + s], u);
    }
}

__global__ void decode_kernel(unsigned* __restrict__ out, int n) {
    int i = blockIdx.x * blockDim.x + threadIdx.x;
    if (i < n) {
        unsigned u = out[i];
        float r;
        if (u == 0u) {
            r = 0.0f;  // untouched segment -> 0 (matches reference)
        } else {
            unsigned bits = (u & 0x80000000u) ? (u ^ 0x80000000u) : ~u;
            r = __uint_as_float(bits);
        }
        ((float*)out)[i] = r;
    }
}

extern "C" void kernel_launch(void* const* d_in, const int* in_sizes, int n_in,
                              void* d_out, int out_size) {
    const float* feats  = (const float*)d_in[0];   // [4,64,512,512] f32
    const int*   labels = (const int*)d_in[1];     // [4,1,512,512] i32
    unsigned*    out    = (unsigned*)d_out;        // [4,64,256] (encoded during accum)

    const int n_out = NB * NCH * NSEG;             // 65536

    init_kernel<<<(n_out + 255) / 256, 256>>>(out, n_out);

    dim3 grid(HWC / CHUNK, NCG, NB);               // (64, 2, 4)
    seg_kernel<<<grid, TPB>>>(feats, labels, out);

    decode_kernel<<<(n_out + 255) / 256, 256>>>(out, n_out);
}